// round 15
// baseline (speedup 1.0000x reference)
#include <cuda_runtime.h>
#include <math.h>
#include <stdint.h>

// Problem constants
#define BATCH   8
#define SEQ     2048
#define DIMS    1024
#define KV      128
#define OUTD    1152
#define NROWS   (BATCH*SEQ)
#define SCALE   0.08838834764831845f

// Attention tiling (R8 measured-best config)
#define BQ      64
#define BK      64
#define HD      128

__device__ float g_keys[NROWS * KV];
__device__ float g_vals[NROWS * KV];

// ---------------------------------------------------------------------------
// helpers
// ---------------------------------------------------------------------------
__device__ __forceinline__ uint32_t f2tf(float f) {
    uint32_t u;
    asm("cvt.rna.tf32.f32 %0, %1;" : "=r"(u) : "f"(f));
    return u;
}
__device__ __forceinline__ uint32_t u2tf(uint32_t raw) {
    uint32_t u;
    asm("cvt.rna.tf32.f32 %0, %1;" : "=r"(u) : "f"(__uint_as_float(raw)));
    return u;
}
__device__ __forceinline__ void mma8(float* c, const uint32_t* a, const uint32_t* b) {
    asm volatile(
        "mma.sync.aligned.m16n8k8.row.col.f32.tf32.tf32.f32 "
        "{%0,%1,%2,%3}, {%4,%5,%6,%7}, {%8,%9}, {%0,%1,%2,%3};"
        : "+f"(c[0]), "+f"(c[1]), "+f"(c[2]), "+f"(c[3])
        : "r"(a[0]), "r"(a[1]), "r"(a[2]), "r"(a[3]), "r"(b[0]), "r"(b[1]));
}
__device__ __forceinline__ void cp16(uint32_t smem_addr, const void* gptr) {
    asm volatile("cp.async.cg.shared.global [%0], [%1], 16;"
                 :: "r"(smem_addr), "l"(gptr));
}
__device__ __forceinline__ void cp_commit() {
    asm volatile("cp.async.commit_group;");
}

extern __shared__ uint32_t dsm[];

// ---------------------------------------------------------------------------
// Kernel 1: projections, SPLIT (y=0 keys / y=1 vals), cp.async double-buffered,
// rna-rounded fragments. Fused X->out copy on y==0. (Best-measured variant:
// R12 "rest" = 106.8 us.) CTA: 128x128, k-chunk 32, 8 warps 2(m)x4(n).
// ---------------------------------------------------------------------------
#define P_AS_W   (128*36)
#define P_WS_W   (32*136)
#define PROJ_SMEM_WORDS (2*P_AS_W + 2*P_WS_W)
#define PROJ_SMEM_BYTES (PROJ_SMEM_WORDS * 4)

__global__ __launch_bounds__(256, 2)
void proj_tc_kernel(const float* __restrict__ x,
                    const float* __restrict__ Wkp, const float* __restrict__ bkp,
                    const float* __restrict__ Wvp, const float* __restrict__ bvp,
                    float* __restrict__ out) {
    uint32_t* As0 = dsm;                     // [2][128][36]
    uint32_t* Ws0 = dsm + 2 * P_AS_W;        // [2][32][136]

    const float* W    = (blockIdx.y == 0) ? Wkp : Wvp;
    const float* bias = (blockIdx.y == 0) ? bkp : bvp;
    float*       outp = (blockIdx.y == 0) ? g_keys : g_vals;

    const int row0 = blockIdx.x * 128;
    const int tid  = threadIdx.x;
    const int wid  = tid >> 5;
    const int lane = tid & 31;
    const int g    = lane >> 2;
    const int tig  = lane & 3;
    const int wm   = (wid >> 2) * 64;
    const int wn   = (wid & 3) * 32;

    const int am = tid >> 1;                 // 0..127
    const int ak = (tid & 1) * 16;
    const int bkr = tid >> 3;                // 0..31
    const int bn  = (tid & 7) * 16;

    const uint32_t as_base = (uint32_t)__cvta_generic_to_shared(As0)
                           + (uint32_t)(am * 36 + ak) * 4u;
    const uint32_t ws_base = (uint32_t)__cvta_generic_to_shared(Ws0)
                           + (uint32_t)(bkr * 136 + bn) * 4u;
    const float* xrow = x + (size_t)(row0 + am) * DIMS + ak;
    const float* wrow = W + (size_t)bkr * KV + bn;

    float acc[4][4][4];
    #pragma unroll
    for (int mt = 0; mt < 4; mt++)
        #pragma unroll
        for (int nt = 0; nt < 4; nt++)
            #pragma unroll
            for (int i = 0; i < 4; i++) acc[mt][nt][i] = 0.0f;

    #pragma unroll
    for (int i = 0; i < 16; i += 4) {
        cp16(as_base + i * 4u, xrow + i);
        cp16(ws_base + i * 4u, wrow + i);
    }
    cp_commit();

    for (int it = 0; it < DIMS / 32; it++) {
        const int cur = it & 1;
        if (it < DIMS / 32 - 1) {
            const uint32_t ao = (uint32_t)((cur ^ 1) * P_AS_W) * 4u;
            const uint32_t wo = (uint32_t)((cur ^ 1) * P_WS_W) * 4u;
            const float* xp = xrow + (it + 1) * 32;
            const float* wp = wrow + (size_t)(it + 1) * 32 * KV;
            #pragma unroll
            for (int i = 0; i < 16; i += 4) {
                cp16(as_base + ao + i * 4u, xp + i);
                cp16(ws_base + wo + i * 4u, wp + i);
            }
            cp_commit();
            asm volatile("cp.async.wait_group 1;");
        } else {
            asm volatile("cp.async.wait_group 0;");
        }
        __syncthreads();

        const uint32_t* As = As0 + cur * P_AS_W;
        const uint32_t* Ws = Ws0 + cur * P_WS_W;

        // fused X->out copy (y==0): raw bits in As are the original floats
        if (blockIdx.y == 0) {
            float* op = out + (size_t)(row0 + am) * OUTD + it * 32 + ak;
            #pragma unroll
            for (int j = 0; j < 8; j++) {
                float2 v = *(const float2*)&As[am * 36 + ak + 2 * j];
                *(float2*)(op + 2 * j) = v;
            }
        }

        #pragma unroll
        for (int ks = 0; ks < 4; ks++) {
            const int k0 = ks * 8;
            uint32_t b[4][2];
            #pragma unroll
            for (int nt = 0; nt < 4; nt++) {
                const int n = wn + nt * 8 + g;
                b[nt][0] = u2tf(Ws[(k0 + tig) * 136 + n]);
                b[nt][1] = u2tf(Ws[(k0 + tig + 4) * 136 + n]);
            }
            #pragma unroll
            for (int mt = 0; mt < 4; mt++) {
                const int m = wm + mt * 16;
                uint32_t a[4];
                a[0] = u2tf(As[(m + g) * 36 + k0 + tig]);
                a[1] = u2tf(As[(m + g + 8) * 36 + k0 + tig]);
                a[2] = u2tf(As[(m + g) * 36 + k0 + tig + 4]);
                a[3] = u2tf(As[(m + g + 8) * 36 + k0 + tig + 4]);
                #pragma unroll
                for (int nt = 0; nt < 4; nt++)
                    mma8(acc[mt][nt], a, b[nt]);
            }
        }
        __syncthreads();
    }

    #pragma unroll
    for (int nt = 0; nt < 4; nt++) {
        const int c0 = wn + nt * 8 + 2 * tig;
        const float b0 = bias[c0], b1 = bias[c0 + 1];
        #pragma unroll
        for (int mt = 0; mt < 4; mt++) {
            const int r0 = row0 + wm + mt * 16 + g;
            float2 lo = make_float2(acc[mt][nt][0] + b0, acc[mt][nt][1] + b1);
            float2 hi = make_float2(acc[mt][nt][2] + b0, acc[mt][nt][3] + b1);
            *(float2*)(outp + (size_t)r0 * KV + c0)       = lo;
            *(float2*)(outp + (size_t)(r0 + 8) * KV + c0) = hi;
        }
    }
}

// ---------------------------------------------------------------------------
// Kernel 2: FA2-style causal flash attention — EXACT R8 config (measured
// 128.7-129 us): BQ=64, BK=64, 128 threads = 4 warps, warp owns 16 q-rows.
// Register softmax; per-warp P strip; 2 block barriers per tile (K/V ring).
// ---------------------------------------------------------------------------
#define KS_STRIDE 132
#define VS_STRIDE 136
#define PW_STRIDE 68

#define KS_WORDS (64*KS_STRIDE)
#define VS_WORDS (64*VS_STRIDE)

#define SM_KS 0
#define SM_VS (SM_KS + 2*KS_WORDS)
#define SM_PW (SM_VS + 2*VS_WORDS)      // 4 warps x 16 rows x PW_STRIDE
#define ATTN_SMEM_WORDS (SM_PW + 4*16*PW_STRIDE)
#define ATTN_SMEM_BYTES (ATTN_SMEM_WORDS * 4)

__global__ __launch_bounds__(128, 1)
void attn_tc_kernel(float* __restrict__ out) {
    const int bid = blockIdx.x;
    const int b   = bid % BATCH;
    const int qb  = (SEQ / BQ - 1) - bid / BATCH;   // heavy blocks first

    const int tid  = threadIdx.x;
    const int wid  = tid >> 5;
    const int lane = tid & 31;
    const int g    = lane >> 2;
    const int tig  = lane & 3;

    uint32_t* Pw = dsm + SM_PW + wid * 16 * PW_STRIDE;   // per-warp strip

    // K/V gmem->smem mapping: r = tid/2 (0..63), k0 = (tid&1)*64  (16x 16B each)
    const int ldr = tid >> 1;
    const int ldk = (tid & 1) * 64;
    const float* gkb = g_keys + (size_t)(b * SEQ + ldr) * KV + ldk;
    const float* gvb = g_vals + (size_t)(b * SEQ + ldr) * KV + ldk;
    const uint32_t ks_base = (uint32_t)__cvta_generic_to_shared(dsm + SM_KS)
                           + (uint32_t)(ldr * KS_STRIDE + ldk) * 4u;
    const uint32_t vs_base = (uint32_t)__cvta_generic_to_shared(dsm + SM_VS)
                           + (uint32_t)(ldr * VS_STRIDE + ldk) * 4u;

    // ---- prefetch tile 0 into buffer 0 ----
    {
        #pragma unroll
        for (int i = 0; i < 64; i += 4) {
            cp16(ks_base + i * 4u, gkb + i);
            cp16(vs_base + i * 4u, gvb + i);
        }
        cp_commit();
    }

    // ---- Q fragments: rows qb*64 + wid*16 .. +15, all 128 k. Register-resident.
    uint32_t aq[16][4];
    {
        const float* gq = g_keys + (size_t)(b * SEQ + qb * BQ + wid * 16) * KV;
        #pragma unroll
        for (int ks = 0; ks < 16; ks++) {
            const int k0 = ks * 8;
            aq[ks][0] = f2tf(gq[(size_t)g * KV + k0 + tig]);
            aq[ks][1] = f2tf(gq[(size_t)(g + 8) * KV + k0 + tig]);
            aq[ks][2] = f2tf(gq[(size_t)g * KV + k0 + tig + 4]);
            aq[ks][3] = f2tf(gq[(size_t)(g + 8) * KV + k0 + tig + 4]);
        }
    }

    float m_lo = -1e30f, m_hi = -1e30f, l_lo = 0.0f, l_hi = 0.0f;

    float o[16][4];
    #pragma unroll
    for (int nt = 0; nt < 16; nt++)
        #pragma unroll
        for (int i = 0; i < 4; i++) o[nt][i] = 0.0f;

    for (int kb = 0; kb <= qb; kb++) {
        const int cur = kb & 1;
        const uint32_t* Ks = dsm + SM_KS + cur * KS_WORDS;
        const uint32_t* Vs = dsm + SM_VS + cur * VS_WORDS;

        __syncthreads();   // all warps done reading buffer cur (prev round)

        if (kb < qb) {
            const uint32_t koff = (uint32_t)((cur ^ 1) * KS_WORDS) * 4u;
            const uint32_t voff = (uint32_t)((cur ^ 1) * VS_WORDS) * 4u;
            const float* gk = gkb + (size_t)(kb + 1) * BK * KV;
            const float* gv = gvb + (size_t)(kb + 1) * BK * KV;
            #pragma unroll
            for (int i = 0; i < 64; i += 4) {
                cp16(ks_base + koff + i * 4u, gk + i);
                cp16(vs_base + voff + i * 4u, gv + i);
            }
            cp_commit();
            asm volatile("cp.async.wait_group 1;");
        } else {
            asm volatile("cp.async.wait_group 0;");
        }
        __syncthreads();   // tile kb visible to all threads

        // ---- phase 1: S = Q @ K^T, full width (8 n-tiles of 8) ----
        float sacc[8][4];
        #pragma unroll
        for (int nt = 0; nt < 8; nt++)
            #pragma unroll
            for (int i = 0; i < 4; i++) sacc[nt][i] = 0.0f;

        #pragma unroll
        for (int ks = 0; ks < 16; ks++) {
            const int k0 = ks * 8;
            uint32_t bfr[8][2];
            #pragma unroll
            for (int nt = 0; nt < 8; nt++) {
                const int tr = nt * 8 + g;
                bfr[nt][0] = Ks[tr * KS_STRIDE + k0 + tig];
                bfr[nt][1] = Ks[tr * KS_STRIDE + k0 + tig + 4];
            }
            #pragma unroll
            for (int nt = 0; nt < 8; nt++)
                mma8(sacc[nt], aq[ks], bfr[nt]);
        }

        // ---- scale + causal mask (only diagonal tile needs it) ----
        const int r_lo = wid * 16 + g;       // row within 64 (kb==qb frame)
        const int r_hi = r_lo + 8;
        #pragma unroll
        for (int nt = 0; nt < 8; nt++) {
            const int c0 = nt * 8 + 2 * tig;
            if (kb == qb) {
                sacc[nt][0] = (c0     > r_lo) ? -1e30f : sacc[nt][0] * SCALE;
                sacc[nt][1] = (c0 + 1 > r_lo) ? -1e30f : sacc[nt][1] * SCALE;
                sacc[nt][2] = (c0     > r_hi) ? -1e30f : sacc[nt][2] * SCALE;
                sacc[nt][3] = (c0 + 1 > r_hi) ? -1e30f : sacc[nt][3] * SCALE;
            } else {
                sacc[nt][0] *= SCALE; sacc[nt][1] *= SCALE;
                sacc[nt][2] *= SCALE; sacc[nt][3] *= SCALE;
            }
        }

        // ---- register online softmax (quad shfl reductions) ----
        float tmax_lo = -1e30f, tmax_hi = -1e30f;
        #pragma unroll
        for (int nt = 0; nt < 8; nt++) {
            tmax_lo = fmaxf(tmax_lo, fmaxf(sacc[nt][0], sacc[nt][1]));
            tmax_hi = fmaxf(tmax_hi, fmaxf(sacc[nt][2], sacc[nt][3]));
        }
        tmax_lo = fmaxf(tmax_lo, __shfl_xor_sync(0xffffffffu, tmax_lo, 1));
        tmax_lo = fmaxf(tmax_lo, __shfl_xor_sync(0xffffffffu, tmax_lo, 2));
        tmax_hi = fmaxf(tmax_hi, __shfl_xor_sync(0xffffffffu, tmax_hi, 1));
        tmax_hi = fmaxf(tmax_hi, __shfl_xor_sync(0xffffffffu, tmax_hi, 2));

        const float mn_lo = fmaxf(m_lo, tmax_lo);
        const float mn_hi = fmaxf(m_hi, tmax_hi);
        const float al_lo = __expf(m_lo - mn_lo);
        const float al_hi = __expf(m_hi - mn_hi);
        m_lo = mn_lo; m_hi = mn_hi;

        float sum_lo = 0.0f, sum_hi = 0.0f;
        #pragma unroll
        for (int nt = 0; nt < 8; nt++) {
            uint32_t p0 = f2tf(__expf(sacc[nt][0] - mn_lo));
            uint32_t p1 = f2tf(__expf(sacc[nt][1] - mn_lo));
            uint32_t p2 = f2tf(__expf(sacc[nt][2] - mn_hi));
            uint32_t p3 = f2tf(__expf(sacc[nt][3] - mn_hi));
            sum_lo += __uint_as_float(p0) + __uint_as_float(p1);
            sum_hi += __uint_as_float(p2) + __uint_as_float(p3);
            sacc[nt][0] = __uint_as_float(p0);
            sacc[nt][1] = __uint_as_float(p1);
            sacc[nt][2] = __uint_as_float(p2);
            sacc[nt][3] = __uint_as_float(p3);
        }
        sum_lo += __shfl_xor_sync(0xffffffffu, sum_lo, 1);
        sum_lo += __shfl_xor_sync(0xffffffffu, sum_lo, 2);
        sum_hi += __shfl_xor_sync(0xffffffffu, sum_hi, 1);
        sum_hi += __shfl_xor_sync(0xffffffffu, sum_hi, 2);
        l_lo = l_lo * al_lo + sum_lo;
        l_hi = l_hi * al_hi + sum_hi;

        // ---- P c-frag -> per-warp smem strip (warp-private, syncwarp only) ----
        __syncwarp();
        #pragma unroll
        for (int nt = 0; nt < 8; nt++) {
            const int pc = nt * 8 + 2 * tig;
            *(float2*)&Pw[g * PW_STRIDE + pc] =
                make_float2(sacc[nt][0], sacc[nt][1]);
            *(float2*)&Pw[(g + 8) * PW_STRIDE + pc] =
                make_float2(sacc[nt][2], sacc[nt][3]);
        }
        __syncwarp();

        // ---- phase 2: O = O*alpha + P @ V, full width (16 n-tiles) ----
        #pragma unroll
        for (int nt = 0; nt < 16; nt++) {
            o[nt][0] *= al_lo; o[nt][1] *= al_lo;
            o[nt][2] *= al_hi; o[nt][3] *= al_hi;
        }
        #pragma unroll
        for (int ks = 0; ks < 8; ks++) {
            const int k0 = ks * 8;
            uint32_t ap[4];
            ap[0] = Pw[g * PW_STRIDE + k0 + tig];
            ap[1] = Pw[(g + 8) * PW_STRIDE + k0 + tig];
            ap[2] = Pw[g * PW_STRIDE + k0 + tig + 4];
            ap[3] = Pw[(g + 8) * PW_STRIDE + k0 + tig + 4];
            #pragma unroll
            for (int nt = 0; nt < 16; nt++) {
                const int d = nt * 8 + g;
                uint32_t bv[2];
                bv[0] = Vs[(k0 + tig) * VS_STRIDE + d];
                bv[1] = Vs[(k0 + tig + 4) * VS_STRIDE + d];
                mma8(o[nt], ap, bv);
            }
        }
    }

    // ---- epilogue: normalize, store ----
    {
        const float inv_lo = 1.0f / l_lo;
        const float inv_hi = 1.0f / l_hi;
        const int row_lo = qb * BQ + wid * 16 + g;
        float* op_lo = out + (size_t)(b * SEQ + row_lo) * OUTD + DIMS;
        float* op_hi = out + (size_t)(b * SEQ + row_lo + 8) * OUTD + DIMS;
        #pragma unroll
        for (int nt = 0; nt < 16; nt++) {
            const int d = nt * 8 + 2 * tig;
            *(float2*)(op_lo + d) = make_float2(o[nt][0] * inv_lo, o[nt][1] * inv_lo);
            *(float2*)(op_hi + d) = make_float2(o[nt][2] * inv_hi, o[nt][3] * inv_hi);
        }
    }
}

// ---------------------------------------------------------------------------
// Launch
// ---------------------------------------------------------------------------
extern "C" void kernel_launch(void* const* d_in, const int* in_sizes, int n_in,
                              void* d_out, int out_size) {
    const float* x   = (const float*)d_in[0];
    const float* Wk  = (const float*)d_in[1];
    const float* bk  = (const float*)d_in[2];
    const float* Wv  = (const float*)d_in[3];
    const float* bv  = (const float*)d_in[4];
    float* out = (float*)d_out;

    cudaFuncSetAttribute(proj_tc_kernel, cudaFuncAttributeMaxDynamicSharedMemorySize,
                         PROJ_SMEM_BYTES);
    proj_tc_kernel<<<dim3(NROWS / 128, 2), 256, PROJ_SMEM_BYTES>>>(x, Wk, bk, Wv, bv, out);

    cudaFuncSetAttribute(attn_tc_kernel, cudaFuncAttributeMaxDynamicSharedMemorySize,
                         ATTN_SMEM_BYTES);
    attn_tc_kernel<<<BATCH * (SEQ / BQ), 128, ATTN_SMEM_BYTES>>>(out);
}

// round 16
// speedup vs baseline: 1.1139x; 1.1139x over previous
#include <cuda_runtime.h>
#include <math.h>
#include <stdint.h>

// Problem constants
#define BATCH   8
#define SEQ     2048
#define DIMS    1024
#define KV      128
#define OUTD    1152
#define NROWS   (BATCH*SEQ)
#define SCALE   0.08838834764831845f

// Attention tiling (R8 measured-best config)
#define BQ      64
#define BK      64
#define HD      128

// g_keys: per row, columns stored INTERLEAVED within each 8-col group:
//   col c -> word pos 8*(c/8) + 2*(c&3) + ((c&7)>>2)
//   => fragment pair (k0+tig, k0+tig+4) lands at adjacent words (LDG/LDS.64)
// g_vals: rows PAIRED: row r -> pair p=(r/8)*4+(r&3), elem e=(r&7)>>2;
//   word idx = p*256 + c*2 + e  => fragment pair (t, t+4) adjacent per d.
__device__ float g_keys[NROWS * KV];
__device__ float g_vals[NROWS * KV];

__device__ __host__ __forceinline__ int kpos(int c) {
    return ((c >> 3) << 3) + ((c & 3) << 1) + ((c & 7) >> 2);
}

// ---------------------------------------------------------------------------
// helpers
// ---------------------------------------------------------------------------
__device__ __forceinline__ uint32_t f2tf(float f) {
    uint32_t u;
    asm("cvt.rna.tf32.f32 %0, %1;" : "=r"(u) : "f"(f));
    return u;
}
__device__ __forceinline__ void mma8(float* c, const uint32_t* a, const uint32_t* b) {
    asm volatile(
        "mma.sync.aligned.m16n8k8.row.col.f32.tf32.tf32.f32 "
        "{%0,%1,%2,%3}, {%4,%5,%6,%7}, {%8,%9}, {%0,%1,%2,%3};"
        : "+f"(c[0]), "+f"(c[1]), "+f"(c[2]), "+f"(c[3])
        : "r"(a[0]), "r"(a[1]), "r"(a[2]), "r"(a[3]), "r"(b[0]), "r"(b[1]));
}
__device__ __forceinline__ void cp16(uint32_t smem_addr, const void* gptr) {
    asm volatile("cp.async.cg.shared.global [%0], [%1], 16;"
                 :: "r"(smem_addr), "l"(gptr));
}
__device__ __forceinline__ void cp_commit() {
    asm volatile("cp.async.commit_group;");
}

// ---------------------------------------------------------------------------
// Kernel 1: projections — R8 measured-best form (LDG + f2tf-on-store, occ 2,
// single-buffer), split y=0 keys / y=1 vals, fused X->out copy on y==0.
// ONLY the epilogue changes: emits interleaved keys / paired vals layouts.
// ---------------------------------------------------------------------------
__global__ __launch_bounds__(256, 2)
void proj_tc_kernel(const float* __restrict__ x,
                    const float* __restrict__ Wkp, const float* __restrict__ bkp,
                    const float* __restrict__ Wvp, const float* __restrict__ bvp,
                    float* __restrict__ out) {
    __shared__ uint32_t As[128][36];
    __shared__ uint32_t Ws[32][136];

    const float* W    = (blockIdx.y == 0) ? Wkp : Wvp;
    const float* bias = (blockIdx.y == 0) ? bkp : bvp;

    const int row0 = blockIdx.x * 128;
    const int tid  = threadIdx.x;
    const int wid  = tid >> 5;
    const int lane = tid & 31;
    const int g    = lane >> 2;
    const int tig  = lane & 3;
    const int wm   = (wid >> 2) * 64;
    const int wn   = (wid & 3) * 32;

    const int am = tid >> 1;
    const int ak = (tid & 1) * 16;
    const int bkr = tid >> 3;
    const int bn  = (tid & 7) * 16;

    float acc[4][4][4];
    #pragma unroll
    for (int mt = 0; mt < 4; mt++)
        #pragma unroll
        for (int nt = 0; nt < 4; nt++)
            #pragma unroll
            for (int i = 0; i < 4; i++) acc[mt][nt][i] = 0.0f;

    for (int kc = 0; kc < DIMS; kc += 32) {
        {
            const float* xp = x + (size_t)(row0 + am) * DIMS + kc + ak;
            float* op = out + (size_t)(row0 + am) * OUTD + kc + ak;
            #pragma unroll
            for (int i = 0; i < 4; i++) {
                float4 v = *(const float4*)(xp + i * 4);
                if (blockIdx.y == 0) *(float4*)(op + i * 4) = v;
                uint4 t;
                t.x = f2tf(v.x); t.y = f2tf(v.y); t.z = f2tf(v.z); t.w = f2tf(v.w);
                *(uint4*)&As[am][ak + i * 4] = t;
            }
        }
        {
            const float* wp = W + (size_t)(kc + bkr) * KV + bn;
            #pragma unroll
            for (int i = 0; i < 4; i++) {
                float4 v = *(const float4*)(wp + i * 4);
                uint4 t;
                t.x = f2tf(v.x); t.y = f2tf(v.y); t.z = f2tf(v.z); t.w = f2tf(v.w);
                *(uint4*)&Ws[bkr][bn + i * 4] = t;
            }
        }
        __syncthreads();

        #pragma unroll
        for (int ks = 0; ks < 4; ks++) {
            const int k0 = ks * 8;
            uint32_t b[4][2];
            #pragma unroll
            for (int nt = 0; nt < 4; nt++) {
                const int n = wn + nt * 8 + g;
                b[nt][0] = Ws[k0 + tig][n];
                b[nt][1] = Ws[k0 + tig + 4][n];
            }
            #pragma unroll
            for (int mt = 0; mt < 4; mt++) {
                const int m = wm + mt * 16;
                uint32_t a[4];
                a[0] = As[m + g][k0 + tig];
                a[1] = As[m + g + 8][k0 + tig];
                a[2] = As[m + g][k0 + tig + 4];
                a[3] = As[m + g + 8][k0 + tig + 4];
                #pragma unroll
                for (int nt = 0; nt < 4; nt++)
                    mma8(acc[mt][nt], a, b[nt]);
            }
        }
        __syncthreads();
    }

    // epilogue: add bias, store into attention-friendly layouts
    #pragma unroll
    for (int nt = 0; nt < 4; nt++) {
        const int c0 = wn + nt * 8 + 2 * tig;
        const float b0 = bias[c0], b1 = bias[c0 + 1];
        #pragma unroll
        for (int mt = 0; mt < 4; mt++) {
            const int r0 = row0 + wm + mt * 16 + g;
            const float v00 = acc[mt][nt][0] + b0;   // (r0,   c0)
            const float v01 = acc[mt][nt][1] + b1;   // (r0,   c0+1)
            const float v10 = acc[mt][nt][2] + b0;   // (r0+8, c0)
            const float v11 = acc[mt][nt][3] + b1;   // (r0+8, c0+1)
            if (blockIdx.y == 0) {
                const int p0 = kpos(c0), p1 = kpos(c0 + 1);
                float* klo = g_keys + (size_t)r0 * KV;
                float* khi = g_keys + (size_t)(r0 + 8) * KV;
                klo[p0] = v00; klo[p1] = v01;
                khi[p0] = v10; khi[p1] = v11;
            } else {
                // paired V layout: idx(r,c) = ((r>>3)*4 + (r&3))*256 + c*2 + ((r&7)>>2)
                const size_t i0 = ((size_t)((r0 >> 3) * 4 + (r0 & 3))) * 256
                                + (size_t)c0 * 2 + ((r0 & 7) >> 2);
                g_vals[i0]        = v00;
                g_vals[i0 + 2]    = v01;
                g_vals[i0 + 1024] = v10;   // r0+8: next 8-group, same w4/e
                g_vals[i0 + 1026] = v11;
            }
        }
    }
}

// ---------------------------------------------------------------------------
// Kernel 2: FA2-style causal flash attention (R8 skeleton), with vectorized
// fragment loads enabled by the producer-side layouts:
//   K smem rows interleaved -> phase-1 B-frags via single LDS.64
//   V smem row-paired       -> phase-2 B-frags via single LDS.64
//   Q fragments             -> LDG.64 pairs
// KS_STRIDE=136 (tr-bank 8g+2tig, half-warp distinct); V pair stride 264.
// ---------------------------------------------------------------------------
#define KS_STRIDE 136
#define VP_STRIDE 264
#define PW_STRIDE 68

#define KS_WORDS (64*KS_STRIDE)     // 8704
#define VS_WORDS (32*VP_STRIDE)     // 8448

#define SM_KS 0
#define SM_VS (SM_KS + 2*KS_WORDS)
#define SM_PW (SM_VS + 2*VS_WORDS)
#define ATTN_SMEM_WORDS (SM_PW + 4*16*PW_STRIDE)
#define ATTN_SMEM_BYTES (ATTN_SMEM_WORDS * 4)

extern __shared__ uint32_t dsm[];

__global__ __launch_bounds__(128, 1)
void attn_tc_kernel(float* __restrict__ out) {
    const int bid = blockIdx.x;
    const int b   = bid % BATCH;
    const int qb  = (SEQ / BQ - 1) - bid / BATCH;   // heavy blocks first

    const int tid  = threadIdx.x;
    const int wid  = tid >> 5;
    const int lane = tid & 31;
    const int g    = lane >> 2;
    const int tig  = lane & 3;

    uint32_t* Pw = dsm + SM_PW + wid * 16 * PW_STRIDE;   // per-warp strip

    const float* gKbat = g_keys + (size_t)(b * SEQ) * KV;
    const float* gVbat = g_vals + (size_t)(b * SEQ) * KV;  // paired layout, tile = 8192 words
    const uint32_t ks_smem = (uint32_t)__cvta_generic_to_shared(dsm + SM_KS);
    const uint32_t vs_smem = (uint32_t)__cvta_generic_to_shared(dsm + SM_VS);

    // ---- tile loader: 2048 16B chunks per array, 16 per thread, coalesced ----
    // K chunk c: row r=c>>5, word o=(c&31)*4 ; dst row stride 136
    // V chunk c: pair p=c>>6, word o=(c&63)*4 ; dst pair stride 264
    auto load_tile = [&](int kb, int buf) {
        const float* gK = gKbat + (size_t)kb * BK * KV;
        const float* gV = gVbat + (size_t)kb * BK * KV;
        const uint32_t kb_dst = ks_smem + (uint32_t)(buf * KS_WORDS) * 4u;
        const uint32_t vb_dst = vs_smem + (uint32_t)(buf * VS_WORDS) * 4u;
        #pragma unroll
        for (int j = 0; j < 16; j++) {
            const int c = j * 128 + tid;
            const int r = c >> 5, o = (c & 31) * 4;
            cp16(kb_dst + (uint32_t)(r * KS_STRIDE + o) * 4u, gK + r * KV + o);
            const int p = c >> 6, o2 = (c & 63) * 4;
            cp16(vb_dst + (uint32_t)(p * VP_STRIDE + o2) * 4u, gV + p * 256 + o2);
        }
        cp_commit();
    };

    // ---- prefetch tile 0 ----
    load_tile(0, 0);

    // ---- Q fragments (interleaved rows -> LDG.64 pairs), rna-rounded ----
    uint32_t aq[16][4];
    {
        const float* gq = gKbat + (size_t)(qb * BQ + wid * 16) * KV;
        #pragma unroll
        for (int ks = 0; ks < 16; ks++) {
            const int w0 = 8 * ks + 2 * tig;
            float2 qlo = *(const float2*)(gq + (size_t)g * KV + w0);
            float2 qhi = *(const float2*)(gq + (size_t)(g + 8) * KV + w0);
            aq[ks][0] = f2tf(qlo.x);
            aq[ks][2] = f2tf(qlo.y);
            aq[ks][1] = f2tf(qhi.x);
            aq[ks][3] = f2tf(qhi.y);
        }
    }

    float m_lo = -1e30f, m_hi = -1e30f, l_lo = 0.0f, l_hi = 0.0f;

    float o[16][4];
    #pragma unroll
    for (int nt = 0; nt < 16; nt++)
        #pragma unroll
        for (int i = 0; i < 4; i++) o[nt][i] = 0.0f;

    for (int kb = 0; kb <= qb; kb++) {
        const int cur = kb & 1;
        const uint32_t* Ks = dsm + SM_KS + cur * KS_WORDS;
        const uint32_t* Vs = dsm + SM_VS + cur * VS_WORDS;

        __syncthreads();   // all warps done reading buffer cur (prev round)

        if (kb < qb) {
            load_tile(kb + 1, cur ^ 1);
            asm volatile("cp.async.wait_group 1;");
        } else {
            asm volatile("cp.async.wait_group 0;");
        }
        __syncthreads();   // tile kb visible

        // ---- phase 1: S = Q @ K^T, B-frags via LDS.64 ----
        float sacc[8][4];
        #pragma unroll
        for (int nt = 0; nt < 8; nt++)
            #pragma unroll
            for (int i = 0; i < 4; i++) sacc[nt][i] = 0.0f;

        #pragma unroll
        for (int ks = 0; ks < 16; ks++) {
            const int w0 = 8 * ks + 2 * tig;
            uint32_t bfr[8][2];
            #pragma unroll
            for (int nt = 0; nt < 8; nt++) {
                const int tr = nt * 8 + g;
                uint2 bb = *(const uint2*)&Ks[tr * KS_STRIDE + w0];
                bfr[nt][0] = bb.x;
                bfr[nt][1] = bb.y;
            }
            #pragma unroll
            for (int nt = 0; nt < 8; nt++)
                mma8(sacc[nt], aq[ks], bfr[nt]);
        }

        // ---- scale + causal mask (diagonal tile only) ----
        const int r_lo = wid * 16 + g;
        const int r_hi = r_lo + 8;
        #pragma unroll
        for (int nt = 0; nt < 8; nt++) {
            const int c0 = nt * 8 + 2 * tig;
            if (kb == qb) {
                sacc[nt][0] = (c0     > r_lo) ? -1e30f : sacc[nt][0] * SCALE;
                sacc[nt][1] = (c0 + 1 > r_lo) ? -1e30f : sacc[nt][1] * SCALE;
                sacc[nt][2] = (c0     > r_hi) ? -1e30f : sacc[nt][2] * SCALE;
                sacc[nt][3] = (c0 + 1 > r_hi) ? -1e30f : sacc[nt][3] * SCALE;
            } else {
                sacc[nt][0] *= SCALE; sacc[nt][1] *= SCALE;
                sacc[nt][2] *= SCALE; sacc[nt][3] *= SCALE;
            }
        }

        // ---- register online softmax (quad shfl) ----
        float tmax_lo = -1e30f, tmax_hi = -1e30f;
        #pragma unroll
        for (int nt = 0; nt < 8; nt++) {
            tmax_lo = fmaxf(tmax_lo, fmaxf(sacc[nt][0], sacc[nt][1]));
            tmax_hi = fmaxf(tmax_hi, fmaxf(sacc[nt][2], sacc[nt][3]));
        }
        tmax_lo = fmaxf(tmax_lo, __shfl_xor_sync(0xffffffffu, tmax_lo, 1));
        tmax_lo = fmaxf(tmax_lo, __shfl_xor_sync(0xffffffffu, tmax_lo, 2));
        tmax_hi = fmaxf(tmax_hi, __shfl_xor_sync(0xffffffffu, tmax_hi, 1));
        tmax_hi = fmaxf(tmax_hi, __shfl_xor_sync(0xffffffffu, tmax_hi, 2));

        const float mn_lo = fmaxf(m_lo, tmax_lo);
        const float mn_hi = fmaxf(m_hi, tmax_hi);
        const float al_lo = __expf(m_lo - mn_lo);
        const float al_hi = __expf(m_hi - mn_hi);
        m_lo = mn_lo; m_hi = mn_hi;

        float sum_lo = 0.0f, sum_hi = 0.0f;
        #pragma unroll
        for (int nt = 0; nt < 8; nt++) {
            uint32_t p0 = f2tf(__expf(sacc[nt][0] - mn_lo));
            uint32_t p1 = f2tf(__expf(sacc[nt][1] - mn_lo));
            uint32_t p2 = f2tf(__expf(sacc[nt][2] - mn_hi));
            uint32_t p3 = f2tf(__expf(sacc[nt][3] - mn_hi));
            sum_lo += __uint_as_float(p0) + __uint_as_float(p1);
            sum_hi += __uint_as_float(p2) + __uint_as_float(p3);
            sacc[nt][0] = __uint_as_float(p0);
            sacc[nt][1] = __uint_as_float(p1);
            sacc[nt][2] = __uint_as_float(p2);
            sacc[nt][3] = __uint_as_float(p3);
        }
        sum_lo += __shfl_xor_sync(0xffffffffu, sum_lo, 1);
        sum_lo += __shfl_xor_sync(0xffffffffu, sum_lo, 2);
        sum_hi += __shfl_xor_sync(0xffffffffu, sum_hi, 1);
        sum_hi += __shfl_xor_sync(0xffffffffu, sum_hi, 2);
        l_lo = l_lo * al_lo + sum_lo;
        l_hi = l_hi * al_hi + sum_hi;

        // ---- P c-frag -> per-warp smem strip (syncwarp only) ----
        __syncwarp();
        #pragma unroll
        for (int nt = 0; nt < 8; nt++) {
            const int pc = nt * 8 + 2 * tig;
            *(float2*)&Pw[g * PW_STRIDE + pc] =
                make_float2(sacc[nt][0], sacc[nt][1]);
            *(float2*)&Pw[(g + 8) * PW_STRIDE + pc] =
                make_float2(sacc[nt][2], sacc[nt][3]);
        }
        __syncwarp();

        // ---- phase 2: O = O*alpha + P @ V, V-frags via LDS.64 ----
        #pragma unroll
        for (int nt = 0; nt < 16; nt++) {
            o[nt][0] *= al_lo; o[nt][1] *= al_lo;
            o[nt][2] *= al_hi; o[nt][3] *= al_hi;
        }
        #pragma unroll
        for (int ks = 0; ks < 8; ks++) {
            const int k0 = ks * 8;
            uint32_t ap[4];
            ap[0] = Pw[g * PW_STRIDE + k0 + tig];
            ap[1] = Pw[(g + 8) * PW_STRIDE + k0 + tig];
            ap[2] = Pw[g * PW_STRIDE + k0 + tig + 4];
            ap[3] = Pw[(g + 8) * PW_STRIDE + k0 + tig + 4];
            const int pbase = (ks * 4 + tig) * VP_STRIDE;
            #pragma unroll
            for (int nt = 0; nt < 16; nt++) {
                const int d = nt * 8 + g;
                uint2 vv = *(const uint2*)&Vs[pbase + d * 2];
                uint32_t bv[2];
                bv[0] = vv.x;
                bv[1] = vv.y;
                mma8(o[nt], ap, bv);
            }
        }
    }

    // ---- epilogue: normalize, store ----
    {
        const float inv_lo = 1.0f / l_lo;
        const float inv_hi = 1.0f / l_hi;
        const int row_lo = qb * BQ + wid * 16 + g;
        float* op_lo = out + (size_t)(b * SEQ + row_lo) * OUTD + DIMS;
        float* op_hi = out + (size_t)(b * SEQ + row_lo + 8) * OUTD + DIMS;
        #pragma unroll
        for (int nt = 0; nt < 16; nt++) {
            const int d = nt * 8 + 2 * tig;
            *(float2*)(op_lo + d) = make_float2(o[nt][0] * inv_lo, o[nt][1] * inv_lo);
            *(float2*)(op_hi + d) = make_float2(o[nt][2] * inv_hi, o[nt][3] * inv_hi);
        }
    }
}

// ---------------------------------------------------------------------------
// Launch
// ---------------------------------------------------------------------------
extern "C" void kernel_launch(void* const* d_in, const int* in_sizes, int n_in,
                              void* d_out, int out_size) {
    const float* x   = (const float*)d_in[0];
    const float* Wk  = (const float*)d_in[1];
    const float* bk  = (const float*)d_in[2];
    const float* Wv  = (const float*)d_in[3];
    const float* bv  = (const float*)d_in[4];
    float* out = (float*)d_out;

    proj_tc_kernel<<<dim3(NROWS / 128, 2), 256>>>(x, Wk, bk, Wv, bv, out);

    cudaFuncSetAttribute(attn_tc_kernel, cudaFuncAttributeMaxDynamicSharedMemorySize,
                         ATTN_SMEM_BYTES);
    attn_tc_kernel<<<BATCH * (SEQ / BQ), 128, ATTN_SMEM_BYTES>>>(out);
}